// round 5
// baseline (speedup 1.0000x reference)
#include <cuda_runtime.h>
#include <cuda_bf16.h>
#include <cstdint>

// NASPolicy: 20-step LSTM(128) controller, batch 1, 6-way softmax heads.
// R5: 4-CTA CGA recurrence; per-step sync = DSMEM mbarrier arrive(release.cluster)
//     + local try_wait(acquire.cluster)  [replaces barrier.cluster ~490cyc].
//     Gate->cell combine via warp shuffles (no smem/__syncthreads in loop).
//     Fast __expf-based activations.

#define CELL   128
#define STEPS  20
#define NOUT   6
#define NREC   4
#define NPRE   20
#define ARRIVALS_PER_PHASE 128   // 4 CTAs x 4 warps x 8 lanes

__device__ float        g_xw[STEPS * 4 * CELL];   // precomputed input-path gates
__device__ unsigned int g_ctr[32];                // phase-A arrival counter

__device__ __forceinline__ unsigned int ld_acq_u32(const unsigned int* p) {
    unsigned int v;
    asm volatile("ld.acquire.gpu.u32 %0, [%1];" : "=r"(v) : "l"(p) : "memory");
    return v;
}
__device__ __forceinline__ uint32_t smem_u32(const void* p) {
    uint32_t a;
    asm("{ .reg .u64 t; cvta.to.shared.u64 t, %1; cvt.u32.u64 %0, t; }"
        : "=r"(a) : "l"(p));
    return a;
}
__device__ __forceinline__ uint32_t mapa_rank(uint32_t addr, uint32_t rank) {
    uint32_t r;
    asm("mapa.shared::cluster.u32 %0, %1, %2;" : "=r"(r) : "r"(addr), "r"(rank));
    return r;
}
__device__ __forceinline__ void st_cluster_f32(uint32_t addr, float v) {
    asm volatile("st.shared::cluster.f32 [%0], %1;" :: "r"(addr), "f"(v) : "memory");
}
__device__ __forceinline__ void mbar_init(uint32_t addr, uint32_t count) {
    asm volatile("mbarrier.init.shared.b64 [%0], %1;" :: "r"(addr), "r"(count) : "memory");
}
__device__ __forceinline__ void mbar_arrive_cluster(uint32_t remote_addr) {
    asm volatile("mbarrier.arrive.release.cluster.shared::cluster.b64 _, [%0];"
                 :: "r"(remote_addr) : "memory");
}
__device__ __forceinline__ void mbar_wait_acq_cluster(uint32_t addr, uint32_t parity) {
    uint32_t done;
    asm volatile(
        "{\n\t.reg .pred p;\n\t"
        "mbarrier.try_wait.parity.acquire.cluster.shared::cta.b64 p, [%1], %2;\n\t"
        "selp.b32 %0, 1, 0, p;\n\t}"
        : "=r"(done) : "r"(addr), "r"(parity) : "memory");
    if (!done) {
        asm volatile(
            "{\n\t.reg .pred P1;\n\t"
            "WL_%=:\n\t"
            "mbarrier.try_wait.parity.acquire.cluster.shared::cta.b64 P1, [%0], %1, 0x989680;\n\t"
            "@P1 bra.uni WD_%=;\n\t"
            "bra.uni WL_%=;\n\t"
            "WD_%=:\n\t}"
            :: "r"(addr), "r"(parity) : "memory");
    }
}
__device__ __forceinline__ void cluster_sync() {
    asm volatile("barrier.cluster.arrive.aligned;" ::: "memory");
    asm volatile("barrier.cluster.wait.aligned;"   ::: "memory");
}
__device__ __forceinline__ float fsig(float x) {
    return __fdividef(1.0f, 1.0f + __expf(-x));
}
__device__ __forceinline__ float ftanh(float x) {
    float e = __expf(-2.0f * x);
    return __fdividef(1.0f - e, 1.0f + e);
}

__global__ void reset_ctr_kernel() {
    if (threadIdx.x < 32) g_ctr[threadIdx.x] = 0u;
}

__global__ void __launch_bounds__(128, 1) __cluster_dims__(NREC, 1, 1)
nas_policy_kernel(const int*   __restrict__ net,
                  const float* __restrict__ emb_start,
                  const float* __restrict__ emb_keys,   // [4,6,128]
                  const float* __restrict__ fcW,        // [4,6,128]
                  const float* __restrict__ fcb,        // [4,6]
                  const float* __restrict__ Wih,        // [512,128]
                  const float* __restrict__ Whh,        // [512,128]
                  const float* __restrict__ bih,        // [512]
                  const float* __restrict__ bhh,        // [512]
                  float*       __restrict__ out)        // [20,1,6]
{
    __shared__ __align__(16) float h_hist[(STEPS + 1) * CELL];
    __shared__ __align__(8) uint64_t mbar;
    __shared__ float sh_x[CELL];
    __shared__ float sm_log[5][NOUT];

    const int t = threadIdx.x;
    const int b = blockIdx.x;

    // ---------------- Phase A: xw for step = b ----------------
    if (b == 0) {
        sh_x[t] = emb_start[t];
    } else {
        int ps = b - 1;
        sh_x[t] = emb_keys[(ps & 3) * (NOUT * CELL) + net[ps] * CELL + t];
    }
    __syncthreads();

    #pragma unroll
    for (int gg = 0; gg < 4; gg++) {
        int r = gg * CELL + t;
        const float4* wr = reinterpret_cast<const float4*>(Wih + r * CELL);
        const float4* xr = reinterpret_cast<const float4*>(sh_x);
        float a0 = 0.f, a1 = 0.f, a2 = 0.f, a3 = 0.f;
        #pragma unroll
        for (int i = 0; i < 32; i++) {
            float4 w4 = wr[i];
            float4 x4 = xr[i];
            a0 += w4.x * x4.x; a1 += w4.y * x4.y;
            a2 += w4.z * x4.z; a3 += w4.w * x4.w;
        }
        g_xw[b * (4 * CELL) + r] = (a0 + a1) + (a2 + a3) + bih[r] + bhh[r];
    }
    __threadfence();
    __syncthreads();
    if (t == 0) atomicAdd(&g_ctr[0], 1u);
    if (b >= NREC) return;

    // ---------------- Phase B: cluster recurrence (blocks 0..3) ----------------
    uint32_t rank;
    asm("mov.u32 %0, %%cluster_ctarank;" : "=r"(rank));

    // Thread mapping: all 4 gates of a cell live in ONE warp.
    const int w    = t >> 5;           // warp 0..3
    const int l    = t & 31;           // lane
    const int gate = l >> 3;           // 0..3 (i,f,g,o)
    const int cs   = l & 7;            // cell-sub 0..7
    const int cell_loc = w * 8 + cs;   // 0..31 within this CTA's chunk
    const int grow = gate * CELL + (int)rank * 32 + cell_loc;

    // W_hh row register-resident
    float wreg[CELL];
    {
        const float4* whr = reinterpret_cast<const float4*>(Whh + grow * CELL);
        #pragma unroll
        for (int i = 0; i < 32; i++) {
            float4 v = whr[i];
            wreg[4*i+0] = v.x; wreg[4*i+1] = v.y;
            wreg[4*i+2] = v.z; wreg[4*i+3] = v.w;
        }
    }

    const uint32_t mbar_la = smem_u32(&mbar);
    if (t == 0) mbar_init(mbar_la, ARRIVALS_PER_PHASE);
    h_hist[t] = 0.0f;   // h0 = 0
    __syncthreads();    // init + h0 visible CTA-wide
    cluster_sync();     // all 4 CTAs' mbarrier inits visible before any remote arrive

    uint32_t mbar_remote[NREC];
    #pragma unroll
    for (uint32_t r = 0; r < NREC; r++) mbar_remote[r] = mapa_rank(mbar_la, r);

    if (t == 0) { while (ld_acq_u32(&g_ctr[0]) < NPRE) { } }
    __syncthreads();

    float c = 0.0f;   // cell state, valid in lanes l<8 (cell = rank*32 + cell_loc)

    for (int step = 0; step < STEPS; step++) {
        float xwv = g_xw[step * (4 * CELL) + grow];   // L2 load, hidden under FMAs

        const float4* hr = reinterpret_cast<const float4*>(h_hist + step * CELL);
        float a0 = 0.f, a1 = 0.f, a2 = 0.f, a3 = 0.f;
        #pragma unroll
        for (int i = 0; i < 32; i++) {
            float4 h4 = hr[i];   // broadcast, conflict-free
            a0 += wreg[4*i+0] * h4.x; a1 += wreg[4*i+1] * h4.y;
            a2 += wreg[4*i+2] * h4.z; a3 += wreg[4*i+3] * h4.w;
        }
        float gv = (a0 + a1) + (a2 + a3) + xwv;
        float a  = (gate == 2) ? ftanh(gv) : fsig(gv);   // activate own gate

        // gather 4 gates of cell cs via warp shuffles (no smem, no CTA barrier)
        float iv = __shfl_sync(0xffffffffu, a, cs);
        float fv = __shfl_sync(0xffffffffu, a, 8 + cs);
        float g2 = __shfl_sync(0xffffffffu, a, 16 + cs);
        float ov = __shfl_sync(0xffffffffu, a, 24 + cs);

        if (l < 8) {
            c = fv * c + iv * g2;
            float h = ov * ftanh(c);
            uint32_t la = smem_u32(&h_hist[(step + 1) * CELL + rank * 32 + w * 8 + l]);
            #pragma unroll
            for (uint32_t r = 0; r < NREC; r++)
                st_cluster_f32(mapa_rank(la, r), h);
            #pragma unroll
            for (uint32_t r = 0; r < NREC; r++)
                mbar_arrive_cluster(mbar_remote[r]);   // release orders this lane's stores
        }
        mbar_wait_acq_cluster(mbar_la, (uint32_t)(step & 1));
    }

    // ---------------- Phase C: softmax heads, 5 steps per CTA (smem h) ----------------
    if (t < 5 * NOUT) {
        int sl = t / NOUT;
        int o  = t % NOUT;
        int s  = (int)rank * 5 + sl;
        const float4* hv = reinterpret_cast<const float4*>(h_hist + (s + 1) * CELL);
        const float4* fv = reinterpret_cast<const float4*>(fcW + ((s & 3) * NOUT + o) * CELL);
        float a0 = 0.f, a1 = 0.f, a2 = 0.f, a3 = 0.f;
        #pragma unroll
        for (int i = 0; i < 32; i++) {
            float4 h4 = hv[i];
            float4 w4 = fv[i];
            a0 += h4.x * w4.x; a1 += h4.y * w4.y;
            a2 += h4.z * w4.z; a3 += h4.w * w4.w;
        }
        sm_log[sl][o] = (a0 + a1) + (a2 + a3) + fcb[(s & 3) * NOUT + o];
    }
    __syncthreads();
    if (t < 5) {
        int s = (int)rank * 5 + t;
        float m = sm_log[t][0];
        #pragma unroll
        for (int o = 1; o < NOUT; o++) m = fmaxf(m, sm_log[t][o]);
        float e[NOUT];
        float sum = 0.f;
        #pragma unroll
        for (int o = 0; o < NOUT; o++) { e[o] = expf(sm_log[t][o] - m); sum += e[o]; }
        float inv = 1.0f / sum;
        #pragma unroll
        for (int o = 0; o < NOUT; o++) out[s * NOUT + o] = e[o] * inv;
    }
}

extern "C" void kernel_launch(void* const* d_in, const int* in_sizes, int n_in,
                              void* d_out, int out_size) {
    const int*   net       = (const int*)  d_in[0];
    // d_in[1] = reward (unused)
    const float* emb_start = (const float*)d_in[2];
    const float* emb_keys  = (const float*)d_in[3];
    const float* fcW       = (const float*)d_in[4];
    const float* fcb       = (const float*)d_in[5];
    const float* Wih       = (const float*)d_in[6];
    const float* Whh       = (const float*)d_in[7];
    const float* bih       = (const float*)d_in[8];
    const float* bhh       = (const float*)d_in[9];
    float* out = (float*)d_out;

    reset_ctr_kernel<<<1, 32>>>();
    nas_policy_kernel<<<NPRE, 128>>>(net, emb_start, emb_keys, fcW, fcb,
                                     Wih, Whh, bih, bhh, out);
}

// round 11
// speedup vs baseline: 1.3477x; 1.3477x over previous
#include <cuda_runtime.h>
#include <cuda_bf16.h>
#include <cstdint>

// NASPolicy: 20-step LSTM(128) controller, batch 1, 6-way softmax heads.
// R11 (= R6 resubmit; R10 was an infra failure, kernel never measured):
//   4-CTA CGA, barrier.cluster sync (R4-proven), upgraded compute:
//   256 thr/CTA half-row dot (fma.rn.f32x2 + ld.shared.v2.b64),
//   warp-local gate combine via shuffles, branchless __expf activations,
//   g_xw prefetch inside the cluster-barrier window.

#define CELL   128
#define STEPS  20
#define NOUT   6
#define NREC   4
#define NPRE   20
#define NTH    256

__device__ float        g_xw[STEPS * 512];   // [step][row] input-path gate preacts
__device__ unsigned int g_ctr[32];

__device__ __forceinline__ unsigned int ld_acq_u32(const unsigned int* p) {
    unsigned int v;
    asm volatile("ld.acquire.gpu.u32 %0, [%1];" : "=r"(v) : "l"(p) : "memory");
    return v;
}
__device__ __forceinline__ uint32_t smem_u32(const void* p) {
    uint32_t a;
    asm("{ .reg .u64 t; cvta.to.shared.u64 t, %1; cvt.u32.u64 %0, t; }"
        : "=r"(a) : "l"(p));
    return a;
}
__device__ __forceinline__ uint32_t mapa_rank(uint32_t addr, uint32_t rank) {
    uint32_t r;
    asm("mapa.shared::cluster.u32 %0, %1, %2;" : "=r"(r) : "r"(addr), "r"(rank));
    return r;
}
__device__ __forceinline__ void st_cluster_f32(uint32_t addr, float v) {
    asm volatile("st.shared::cluster.f32 [%0], %1;" :: "r"(addr), "f"(v) : "memory");
}
__device__ __forceinline__ float fsig(float x) {
    return __fdividef(1.0f, 1.0f + __expf(-x));
}

__global__ void reset_ctr_kernel() {
    if (threadIdx.x < 32) g_ctr[threadIdx.x] = 0u;
}

__global__ void __launch_bounds__(NTH, 1) __cluster_dims__(NREC, 1, 1)
nas_policy_kernel(const int*   __restrict__ net,
                  const float* __restrict__ emb_start,
                  const float* __restrict__ emb_keys,   // [4,6,128]
                  const float* __restrict__ fcW,        // [4,6,128]
                  const float* __restrict__ fcb,        // [4,6]
                  const float* __restrict__ Wih,        // [512,128]
                  const float* __restrict__ Whh,        // [512,128]
                  const float* __restrict__ bih,        // [512]
                  const float* __restrict__ bhh,        // [512]
                  float*       __restrict__ out)        // [20,1,6]
{
    __shared__ __align__(16) float h_hist[(STEPS + 1) * CELL];
    __shared__ __align__(16) float sh_x[CELL];
    __shared__ float sm_log[5][NOUT];

    const int t = threadIdx.x;
    const int b = blockIdx.x;

    // ---------------- Phase A: xw rows t and t+256 for step = b ----------------
    if (t < CELL) {
        if (b == 0) sh_x[t] = emb_start[t];
        else {
            int ps = b - 1;
            sh_x[t] = emb_keys[(ps & 3) * (NOUT * CELL) + net[ps] * CELL + t];
        }
    }
    __syncthreads();

    #pragma unroll
    for (int rr = 0; rr < 2; rr++) {
        int r = t + rr * 256;
        const float4* wr = reinterpret_cast<const float4*>(Wih + r * CELL);
        const float4* xr = reinterpret_cast<const float4*>(sh_x);
        float a0 = 0.f, a1 = 0.f, a2 = 0.f, a3 = 0.f;
        #pragma unroll
        for (int i = 0; i < 32; i++) {
            float4 w4 = wr[i];
            float4 x4 = xr[i];
            a0 += w4.x * x4.x; a1 += w4.y * x4.y;
            a2 += w4.z * x4.z; a3 += w4.w * x4.w;
        }
        g_xw[b * 512 + r] = (a0 + a1) + (a2 + a3) + bih[r] + bhh[r];
    }
    __threadfence();
    __syncthreads();
    if (t == 0) atomicAdd(&g_ctr[0], 1u);
    if (b >= NREC) return;

    // ---------------- Phase B: cluster recurrence (blocks 0..3) ----------------
    uint32_t rank;
    asm("mov.u32 %0, %%cluster_ctarank;" : "=r"(rank));

    // Lane map: warp w, lane l. half = l>>4. Within a half: (l&15) = gate*4 + cq.
    // Thread's gate row: grow = gate*128 + rank*32 + (w*4 + cq).
    const int w    = t >> 5;            // 0..7
    const int l    = t & 31;
    const int half = l >> 4;            // 0/1 -> h[0..63] / h[64..127]
    const int gate = (l >> 2) & 3;      // i,f,g,o
    const int cq   = l & 3;             // cell quarter within warp
    const int cell_loc = w * 4 + cq;    // 0..31 in this CTA's chunk
    const int grow = gate * CELL + (int)rank * 32 + cell_loc;

    // Half-row of W_hh register-resident as 32 packed f32x2 (issued before spin)
    uint64_t wq[32];
    {
        const ulonglong2* wp = reinterpret_cast<const ulonglong2*>(Whh + grow * CELL + half * 64);
        #pragma unroll
        for (int i = 0; i < 16; i++) {
            ulonglong2 v = wp[i];
            wq[2*i] = v.x; wq[2*i+1] = v.y;
        }
    }

    if (t < CELL) h_hist[t] = 0.0f;     // h0 = 0
    const uint32_t hbase_la = smem_u32(h_hist);
    uint32_t peer[NREC];
    #pragma unroll
    for (uint32_t r = 0; r < NREC; r++) peer[r] = mapa_rank(hbase_la, r);

    if (t == 0) { while (ld_acq_u32(&g_ctr[0]) < NPRE) { } }
    __syncthreads();

    float c = 0.0f;                      // lanes l<4 own cell rank*32 + w*4 + l
    float xwv = g_xw[grow];              // step 0 input-path preact

    // branchless activation params: tanh(x) = 2*sig(2x)-1
    const float asc  = (gate == 2) ? 2.0f : 1.0f;
    const float aoff = (gate == 2) ? -1.0f : 0.0f;

    for (int step = 0; step < STEPS; step++) {
        // half-row dot: 16x LDS.v2.b64 + 32x fma.rn.f32x2
        uint32_t hb = hbase_la + (uint32_t)(step * CELL * 4 + half * 256);
        uint64_t acc0 = 0ull, acc1 = 0ull;
        #pragma unroll
        for (int i = 0; i < 16; i++) {
            uint64_t h01, h23;
            asm volatile("ld.shared.v2.b64 {%0,%1}, [%2];"
                         : "=l"(h01), "=l"(h23) : "r"(hb + 16u * i));
            asm volatile("fma.rn.f32x2 %0, %1, %2, %0;" : "+l"(acc0) : "l"(wq[2*i]),   "l"(h01));
            asm volatile("fma.rn.f32x2 %0, %1, %2, %0;" : "+l"(acc1) : "l"(wq[2*i+1]), "l"(h23));
        }
        uint64_t accs;
        asm("add.rn.f32x2 %0, %1, %2;" : "=l"(accs) : "l"(acc0), "l"(acc1));
        uint32_t plo, phi;
        asm("mov.b64 {%0,%1}, %2;" : "=r"(plo), "=r"(phi) : "l"(accs));
        float partial = __uint_as_float(plo) + __uint_as_float(phi);

        float full = partial + __shfl_xor_sync(0xffffffffu, partial, 16);
        float gv   = full + xwv;
        float a    = fmaf(asc, fsig(asc * gv), aoff);   // sig or tanh, no branch

        // gather the 4 gates of cell (l&3) via shuffles
        int srcq = l & 3;
        float iv = __shfl_sync(0xffffffffu, a, srcq);
        float fv = __shfl_sync(0xffffffffu, a, 4 + srcq);
        float g2 = __shfl_sync(0xffffffffu, a, 8 + srcq);
        float ov = __shfl_sync(0xffffffffu, a, 12 + srcq);

        if (l < 4) {
            c = fv * c + iv * g2;
            float h = ov * fmaf(2.0f, fsig(2.0f * c), -1.0f);   // ov * tanh(c)
            uint32_t off = (uint32_t)(((step + 1) * CELL + (int)rank * 32 + cell_loc) * 4);
            #pragma unroll
            for (uint32_t r = 0; r < NREC; r++)
                st_cluster_f32(peer[r] + off, h);
        }
        asm volatile("barrier.cluster.arrive.aligned;" ::: "memory");
        if (step + 1 < STEPS) xwv = g_xw[(step + 1) * 512 + grow];  // hide L2 in barrier window
        asm volatile("barrier.cluster.wait.aligned;"   ::: "memory");
    }

    // ---------------- Phase C: softmax heads, 5 steps per CTA ----------------
    if (t < 5 * NOUT) {
        int sl = t / NOUT;
        int o  = t % NOUT;
        int s  = (int)rank * 5 + sl;
        const float4* hv = reinterpret_cast<const float4*>(h_hist + (s + 1) * CELL);
        const float4* fv = reinterpret_cast<const float4*>(fcW + ((s & 3) * NOUT + o) * CELL);
        float a0 = 0.f, a1 = 0.f, a2 = 0.f, a3 = 0.f;
        #pragma unroll
        for (int i = 0; i < 32; i++) {
            float4 h4 = hv[i];
            float4 w4 = fv[i];
            a0 += h4.x * w4.x; a1 += h4.y * w4.y;
            a2 += h4.z * w4.z; a3 += h4.w * w4.w;
        }
        sm_log[sl][o] = (a0 + a1) + (a2 + a3) + fcb[(s & 3) * NOUT + o];
    }
    __syncthreads();
    if (t < 5) {
        int s = (int)rank * 5 + t;
        float m = sm_log[t][0];
        #pragma unroll
        for (int o = 1; o < NOUT; o++) m = fmaxf(m, sm_log[t][o]);
        float e[NOUT];
        float sum = 0.f;
        #pragma unroll
        for (int o = 0; o < NOUT; o++) { e[o] = expf(sm_log[t][o] - m); sum += e[o]; }
        float inv = 1.0f / sum;
        #pragma unroll
        for (int o = 0; o < NOUT; o++) out[s * NOUT + o] = e[o] * inv;
    }
}

extern "C" void kernel_launch(void* const* d_in, const int* in_sizes, int n_in,
                              void* d_out, int out_size) {
    const int*   net       = (const int*)  d_in[0];
    // d_in[1] = reward (unused)
    const float* emb_start = (const float*)d_in[2];
    const float* emb_keys  = (const float*)d_in[3];
    const float* fcW       = (const float*)d_in[4];
    const float* fcb       = (const float*)d_in[5];
    const float* Wih       = (const float*)d_in[6];
    const float* Whh       = (const float*)d_in[7];
    const float* bih       = (const float*)d_in[8];
    const float* bhh       = (const float*)d_in[9];
    float* out = (float*)d_out;

    reset_ctr_kernel<<<1, 32>>>();
    nas_policy_kernel<<<NPRE, NTH>>>(net, emb_start, emb_keys, fcW, fcb,
                                     Wih, Whh, bih, bhh, out);
}

// round 12
// speedup vs baseline: 1.5337x; 1.1380x over previous
#include <cuda_runtime.h>
#include <cuda_bf16.h>
#include <cstdint>

// NASPolicy: 20-step LSTM(128) controller, batch 1, 6-way softmax heads.
// R12: replace barrier.cluster with st.async + mbarrier tx-accounting.
//   4-CTA CGA. Per step: each CTA expects 512B on its local mbarrier;
//   each warp's lane0 fires one st.async.v4.f32 (4 h values) to every rank
//   (store + remote completion signal in ONE instruction); consumers
//   try_wait parity. No cluster barrier, no __syncthreads in the loop.
//   Compute structure = R11 (proven): half-row f32x2 dot, shfl gate combine,
//   branchless __expf activations, g_xw prefetch before the wait.

#define CELL   128
#define STEPS  20
#define NOUT   6
#define NREC   4
#define NPRE   20
#define NTH    256
#define H_BYTES_PER_STEP 512   // 128 floats into each CTA per step

__device__ float        g_xw[STEPS * 512];   // [step][row] input-path gate preacts
__device__ unsigned int g_ctr[32];

__device__ __forceinline__ unsigned int ld_acq_u32(const unsigned int* p) {
    unsigned int v;
    asm volatile("ld.acquire.gpu.u32 %0, [%1];" : "=r"(v) : "l"(p) : "memory");
    return v;
}
__device__ __forceinline__ uint32_t smem_u32(const void* p) {
    uint32_t a;
    asm("{ .reg .u64 t; cvta.to.shared.u64 t, %1; cvt.u32.u64 %0, t; }"
        : "=r"(a) : "l"(p));
    return a;
}
__device__ __forceinline__ uint32_t mapa_rank(uint32_t addr, uint32_t rank) {
    uint32_t r;
    asm("mapa.shared::cluster.u32 %0, %1, %2;" : "=r"(r) : "r"(addr), "r"(rank));
    return r;
}
__device__ __forceinline__ void mbar_init(uint32_t addr, uint32_t count) {
    asm volatile("mbarrier.init.shared.b64 [%0], %1;" :: "r"(addr), "r"(count) : "memory");
}
__device__ __forceinline__ void mbar_arrive_expect_tx(uint32_t addr, uint32_t bytes) {
    asm volatile("mbarrier.arrive.expect_tx.shared.b64 _, [%0], %1;"
                 :: "r"(addr), "r"(bytes) : "memory");
}
// store 16B into peer smem + signal peer mbarrier, one instruction
__device__ __forceinline__ void st_async_v4(uint32_t dst, float h0, float h1,
                                            float h2, float h3, uint32_t peer_mbar) {
    asm volatile(
        "st.async.shared::cluster.mbarrier::complete_tx::bytes.v4.f32 "
        "[%0], {%1,%2,%3,%4}, [%5];"
        :: "r"(dst), "f"(h0), "f"(h1), "f"(h2), "f"(h3), "r"(peer_mbar) : "memory");
}
__device__ __forceinline__ void mbar_wait_parity(uint32_t addr, uint32_t parity) {
    uint32_t done;
    asm volatile(
        "{\n\t.reg .pred p;\n\t"
        "mbarrier.try_wait.parity.acquire.cta.shared::cta.b64 p, [%1], %2;\n\t"
        "selp.b32 %0, 1, 0, p;\n\t}"
        : "=r"(done) : "r"(addr), "r"(parity) : "memory");
    if (!done) {
        asm volatile(
            "{\n\t.reg .pred P1;\n\t"
            "WL_%=:\n\t"
            "mbarrier.try_wait.parity.acquire.cta.shared::cta.b64 P1, [%0], %1, 0x989680;\n\t"
            "@P1 bra.uni WD_%=;\n\t"
            "bra.uni WL_%=;\n\t"
            "WD_%=:\n\t}"
            :: "r"(addr), "r"(parity) : "memory");
    }
}
__device__ __forceinline__ void cluster_sync() {
    asm volatile("barrier.cluster.arrive.aligned;" ::: "memory");
    asm volatile("barrier.cluster.wait.aligned;"   ::: "memory");
}
__device__ __forceinline__ float fsig(float x) {
    return __fdividef(1.0f, 1.0f + __expf(-x));
}

__global__ void reset_ctr_kernel() {
    if (threadIdx.x < 32) g_ctr[threadIdx.x] = 0u;
}

__global__ void __launch_bounds__(NTH, 1) __cluster_dims__(NREC, 1, 1)
nas_policy_kernel(const int*   __restrict__ net,
                  const float* __restrict__ emb_start,
                  const float* __restrict__ emb_keys,   // [4,6,128]
                  const float* __restrict__ fcW,        // [4,6,128]
                  const float* __restrict__ fcb,        // [4,6]
                  const float* __restrict__ Wih,        // [512,128]
                  const float* __restrict__ Whh,        // [512,128]
                  const float* __restrict__ bih,        // [512]
                  const float* __restrict__ bhh,        // [512]
                  float*       __restrict__ out)        // [20,1,6]
{
    __shared__ __align__(16) float h_hist[(STEPS + 1) * CELL];
    __shared__ __align__(16) float sh_x[CELL];
    __shared__ __align__(8)  uint64_t mbar;
    __shared__ float sm_log[5][NOUT];

    const int t = threadIdx.x;
    const int b = blockIdx.x;

    // ---------------- Phase A: xw rows t and t+256 for step = b ----------------
    if (t < CELL) {
        if (b == 0) sh_x[t] = emb_start[t];
        else {
            int ps = b - 1;
            sh_x[t] = emb_keys[(ps & 3) * (NOUT * CELL) + net[ps] * CELL + t];
        }
    }
    __syncthreads();

    #pragma unroll
    for (int rr = 0; rr < 2; rr++) {
        int r = t + rr * 256;
        const float4* wr = reinterpret_cast<const float4*>(Wih + r * CELL);
        const float4* xr = reinterpret_cast<const float4*>(sh_x);
        float a0 = 0.f, a1 = 0.f, a2 = 0.f, a3 = 0.f;
        #pragma unroll
        for (int i = 0; i < 32; i++) {
            float4 w4 = wr[i];
            float4 x4 = xr[i];
            a0 += w4.x * x4.x; a1 += w4.y * x4.y;
            a2 += w4.z * x4.z; a3 += w4.w * x4.w;
        }
        g_xw[b * 512 + r] = (a0 + a1) + (a2 + a3) + bih[r] + bhh[r];
    }
    __threadfence();
    __syncthreads();
    if (t == 0) atomicAdd(&g_ctr[0], 1u);
    if (b >= NREC) return;   // clusters 1..4 fully exit (no cluster ops executed there)

    // ---------------- Phase B: cluster recurrence (blocks 0..3) ----------------
    uint32_t rank;
    asm("mov.u32 %0, %%cluster_ctarank;" : "=r"(rank));

    // Lane map (R11-proven): warp w, lane l. half = l>>4; gate = (l>>2)&3; cq = l&3.
    const int w    = t >> 5;            // 0..7
    const int l    = t & 31;
    const int half = l >> 4;
    const int gate = (l >> 2) & 3;
    const int cq   = l & 3;
    const int cell_loc = w * 4 + cq;    // 0..31 in this CTA's chunk
    const int grow = gate * CELL + (int)rank * 32 + cell_loc;

    // Half-row of W_hh register-resident as packed f32x2
    uint64_t wq[32];
    {
        const ulonglong2* wp = reinterpret_cast<const ulonglong2*>(Whh + grow * CELL + half * 64);
        #pragma unroll
        for (int i = 0; i < 16; i++) {
            ulonglong2 v = wp[i];
            wq[2*i] = v.x; wq[2*i+1] = v.y;
        }
    }

    if (t < CELL) h_hist[t] = 0.0f;     // h0 = 0
    const uint32_t hbase_la = smem_u32(h_hist);
    const uint32_t mbar_la  = smem_u32(&mbar);
    if (t == 0) mbar_init(mbar_la, 1);  // 1 arrival per phase (the expect_tx arrive)
    __syncthreads();
    cluster_sync();                     // all 4 CTAs' mbarrier inits visible

    uint32_t peer_h[NREC], peer_m[NREC];
    #pragma unroll
    for (uint32_t r = 0; r < NREC; r++) {
        peer_h[r] = mapa_rank(hbase_la, r);
        peer_m[r] = mapa_rank(mbar_la, r);
    }

    if (t == 0) { while (ld_acq_u32(&g_ctr[0]) < NPRE) { } }
    __syncthreads();

    float c = 0.0f;                      // lanes l<4 own cell rank*32 + cell_loc
    float xwv = g_xw[grow];

    const float asc  = (gate == 2) ? 2.0f : 1.0f;   // tanh(x) = 2*sig(2x)-1
    const float aoff = (gate == 2) ? -1.0f : 0.0f;

    for (int step = 0; step < STEPS; step++) {
        // raise this phase's tx expectation (races with incoming tx are spec-legal)
        if (t == 0) mbar_arrive_expect_tx(mbar_la, H_BYTES_PER_STEP);

        // half-row dot: 16x LDS.v2.b64 + 32x fma.rn.f32x2
        uint32_t hb = hbase_la + (uint32_t)(step * CELL * 4 + half * 256);
        uint64_t acc0 = 0ull, acc1 = 0ull;
        #pragma unroll
        for (int i = 0; i < 16; i++) {
            uint64_t h01, h23;
            asm volatile("ld.shared.v2.b64 {%0,%1}, [%2];"
                         : "=l"(h01), "=l"(h23) : "r"(hb + 16u * i));
            asm volatile("fma.rn.f32x2 %0, %1, %2, %0;" : "+l"(acc0) : "l"(wq[2*i]),   "l"(h01));
            asm volatile("fma.rn.f32x2 %0, %1, %2, %0;" : "+l"(acc1) : "l"(wq[2*i+1]), "l"(h23));
        }
        uint64_t accs;
        asm("add.rn.f32x2 %0, %1, %2;" : "=l"(accs) : "l"(acc0), "l"(acc1));
        uint32_t plo, phi;
        asm("mov.b64 {%0,%1}, %2;" : "=r"(plo), "=r"(phi) : "l"(accs));
        float partial = __uint_as_float(plo) + __uint_as_float(phi);

        float full = partial + __shfl_xor_sync(0xffffffffu, partial, 16);
        float gv   = full + xwv;
        float a    = fmaf(asc, fsig(asc * gv), aoff);

        // gather the 4 gates of cell (l&3)
        int srcq = l & 3;
        float iv = __shfl_sync(0xffffffffu, a, srcq);
        float fv = __shfl_sync(0xffffffffu, a, 4 + srcq);
        float g2 = __shfl_sync(0xffffffffu, a, 8 + srcq);
        float ov = __shfl_sync(0xffffffffu, a, 12 + srcq);

        // all lanes compute (garbage for l>=4, never read)
        c = fv * c + iv * g2;
        float h = ov * fmaf(2.0f, fsig(2.0f * c), -1.0f);

        // warp's 4 h values -> lane 0, one st.async.v4 per rank
        float h0 = __shfl_sync(0xffffffffu, h, 0);
        float h1 = __shfl_sync(0xffffffffu, h, 1);
        float h2 = __shfl_sync(0xffffffffu, h, 2);
        float h3 = __shfl_sync(0xffffffffu, h, 3);
        if (l == 0) {
            uint32_t off = (uint32_t)(((step + 1) * CELL + (int)rank * 32 + w * 4) * 4);
            #pragma unroll
            for (uint32_t r = 0; r < NREC; r++)
                st_async_v4(peer_h[r] + off, h0, h1, h2, h3, peer_m[r]);
        }

        if (step + 1 < STEPS) xwv = g_xw[(step + 1) * 512 + grow];  // hide L2 latency
        mbar_wait_parity(mbar_la, (uint32_t)(step & 1));
    }

    // ---------------- Phase C: softmax heads, 5 steps per CTA ----------------
    if (t < 5 * NOUT) {
        int sl = t / NOUT;
        int o  = t % NOUT;
        int s  = (int)rank * 5 + sl;
        const float4* hv = reinterpret_cast<const float4*>(h_hist + (s + 1) * CELL);
        const float4* fv = reinterpret_cast<const float4*>(fcW + ((s & 3) * NOUT + o) * CELL);
        float a0 = 0.f, a1 = 0.f, a2 = 0.f, a3 = 0.f;
        #pragma unroll
        for (int i = 0; i < 32; i++) {
            float4 h4 = hv[i];
            float4 w4 = fv[i];
            a0 += h4.x * w4.x; a1 += h4.y * w4.y;
            a2 += h4.z * w4.z; a3 += h4.w * w4.w;
        }
        sm_log[sl][o] = (a0 + a1) + (a2 + a3) + fcb[(s & 3) * NOUT + o];
    }
    __syncthreads();
    if (t < 5) {
        int s = (int)rank * 5 + t;
        float m = sm_log[t][0];
        #pragma unroll
        for (int o = 1; o < NOUT; o++) m = fmaxf(m, sm_log[t][o]);
        float e[NOUT];
        float sum = 0.f;
        #pragma unroll
        for (int o = 0; o < NOUT; o++) { e[o] = expf(sm_log[t][o] - m); sum += e[o]; }
        float inv = 1.0f / sum;
        #pragma unroll
        for (int o = 0; o < NOUT; o++) out[s * NOUT + o] = e[o] * inv;
    }
}

extern "C" void kernel_launch(void* const* d_in, const int* in_sizes, int n_in,
                              void* d_out, int out_size) {
    const int*   net       = (const int*)  d_in[0];
    // d_in[1] = reward (unused)
    const float* emb_start = (const float*)d_in[2];
    const float* emb_keys  = (const float*)d_in[3];
    const float* fcW       = (const float*)d_in[4];
    const float* fcb       = (const float*)d_in[5];
    const float* Wih       = (const float*)d_in[6];
    const float* Whh       = (const float*)d_in[7];
    const float* bih       = (const float*)d_in[8];
    const float* bhh       = (const float*)d_in[9];
    float* out = (float*)d_out;

    reset_ctr_kernel<<<1, 32>>>();
    nas_policy_kernel<<<NPRE, NTH>>>(net, emb_start, emb_keys, fcW, fcb,
                                     Wih, Whh, bih, bhh, out);
}

// round 13
// speedup vs baseline: 1.6678x; 1.0875x over previous
#include <cuda_runtime.h>
#include <cuda_bf16.h>
#include <cstdint>

// NASPolicy: 20-step LSTM(128) controller, batch 1, 6-way softmax heads.
// R13 (over R12): single-launch (counter self-reset at kernel end),
//   MUFU tanh.approx activations (sig(x)=0.5*tanh(0.5x)+0.5),
//   mbarrier re-armed post-wait (off critical path).
//   Core design (R12-proven): 4-CTA CGA, st.async.v4 + mbarrier tx-accounting
//   h-exchange, half-row f32x2 dot, shfl gate combine, g_xw prefetch.

#define CELL   128
#define STEPS  20
#define NOUT   6
#define NREC   4
#define NPRE   20
#define NTH    256
#define H_BYTES_PER_STEP 512   // 128 floats into each CTA per step

__device__ float        g_xw[STEPS * 512];   // [step][row] input-path gate preacts
__device__ unsigned int g_ctr[32];           // zero at load; self-reset at kernel end

__device__ __forceinline__ unsigned int ld_acq_u32(const unsigned int* p) {
    unsigned int v;
    asm volatile("ld.acquire.gpu.u32 %0, [%1];" : "=r"(v) : "l"(p) : "memory");
    return v;
}
__device__ __forceinline__ uint32_t smem_u32(const void* p) {
    uint32_t a;
    asm("{ .reg .u64 t; cvta.to.shared.u64 t, %1; cvt.u32.u64 %0, t; }"
        : "=r"(a) : "l"(p));
    return a;
}
__device__ __forceinline__ uint32_t mapa_rank(uint32_t addr, uint32_t rank) {
    uint32_t r;
    asm("mapa.shared::cluster.u32 %0, %1, %2;" : "=r"(r) : "r"(addr), "r"(rank));
    return r;
}
__device__ __forceinline__ void mbar_init(uint32_t addr, uint32_t count) {
    asm volatile("mbarrier.init.shared.b64 [%0], %1;" :: "r"(addr), "r"(count) : "memory");
}
__device__ __forceinline__ void mbar_arrive_expect_tx(uint32_t addr, uint32_t bytes) {
    asm volatile("mbarrier.arrive.expect_tx.shared.b64 _, [%0], %1;"
                 :: "r"(addr), "r"(bytes) : "memory");
}
// store 16B into peer smem + signal peer mbarrier, one instruction
__device__ __forceinline__ void st_async_v4(uint32_t dst, float h0, float h1,
                                            float h2, float h3, uint32_t peer_mbar) {
    asm volatile(
        "st.async.shared::cluster.mbarrier::complete_tx::bytes.v4.f32 "
        "[%0], {%1,%2,%3,%4}, [%5];"
        :: "r"(dst), "f"(h0), "f"(h1), "f"(h2), "f"(h3), "r"(peer_mbar) : "memory");
}
__device__ __forceinline__ void mbar_wait_parity(uint32_t addr, uint32_t parity) {
    uint32_t done;
    asm volatile(
        "{\n\t.reg .pred p;\n\t"
        "mbarrier.try_wait.parity.acquire.cta.shared::cta.b64 p, [%1], %2;\n\t"
        "selp.b32 %0, 1, 0, p;\n\t}"
        : "=r"(done) : "r"(addr), "r"(parity) : "memory");
    if (!done) {
        asm volatile(
            "{\n\t.reg .pred P1;\n\t"
            "WL_%=:\n\t"
            "mbarrier.try_wait.parity.acquire.cta.shared::cta.b64 P1, [%0], %1, 0x989680;\n\t"
            "@P1 bra.uni WD_%=;\n\t"
            "bra.uni WL_%=;\n\t"
            "WD_%=:\n\t}"
            :: "r"(addr), "r"(parity) : "memory");
    }
}
__device__ __forceinline__ void cluster_sync() {
    asm volatile("barrier.cluster.arrive.aligned;" ::: "memory");
    asm volatile("barrier.cluster.wait.aligned;"   ::: "memory");
}
__device__ __forceinline__ float ftanh_mufu(float x) {
    float r;
    asm("tanh.approx.f32 %0, %1;" : "=f"(r) : "f"(x));
    return r;
}

__global__ void __launch_bounds__(NTH, 1) __cluster_dims__(NREC, 1, 1)
nas_policy_kernel(const int*   __restrict__ net,
                  const float* __restrict__ emb_start,
                  const float* __restrict__ emb_keys,   // [4,6,128]
                  const float* __restrict__ fcW,        // [4,6,128]
                  const float* __restrict__ fcb,        // [4,6]
                  const float* __restrict__ Wih,        // [512,128]
                  const float* __restrict__ Whh,        // [512,128]
                  const float* __restrict__ bih,        // [512]
                  const float* __restrict__ bhh,        // [512]
                  float*       __restrict__ out)        // [20,1,6]
{
    __shared__ __align__(16) float h_hist[(STEPS + 1) * CELL];
    __shared__ __align__(16) float sh_x[CELL];
    __shared__ __align__(8)  uint64_t mbar;
    __shared__ float sm_log[5][NOUT];

    const int t = threadIdx.x;
    const int b = blockIdx.x;

    // ---------------- Phase A: xw rows t and t+256 for step = b ----------------
    if (t < CELL) {
        if (b == 0) sh_x[t] = emb_start[t];
        else {
            int ps = b - 1;
            sh_x[t] = emb_keys[(ps & 3) * (NOUT * CELL) + net[ps] * CELL + t];
        }
    }
    __syncthreads();

    #pragma unroll
    for (int rr = 0; rr < 2; rr++) {
        int r = t + rr * 256;
        const float4* wr = reinterpret_cast<const float4*>(Wih + r * CELL);
        const float4* xr = reinterpret_cast<const float4*>(sh_x);
        float a0 = 0.f, a1 = 0.f, a2 = 0.f, a3 = 0.f;
        #pragma unroll
        for (int i = 0; i < 32; i++) {
            float4 w4 = wr[i];
            float4 x4 = xr[i];
            a0 += w4.x * x4.x; a1 += w4.y * x4.y;
            a2 += w4.z * x4.z; a3 += w4.w * x4.w;
        }
        g_xw[b * 512 + r] = (a0 + a1) + (a2 + a3) + bih[r] + bhh[r];
    }
    __threadfence();
    __syncthreads();
    if (t == 0) atomicAdd(&g_ctr[0], 1u);
    if (b >= NREC) return;   // clusters 1..4 fully exit (no cluster ops there)

    // ---------------- Phase B: cluster recurrence (blocks 0..3) ----------------
    uint32_t rank;
    asm("mov.u32 %0, %%cluster_ctarank;" : "=r"(rank));

    // Lane map: warp w, lane l. half = l>>4; gate = (l>>2)&3; cq = l&3.
    const int w    = t >> 5;            // 0..7
    const int l    = t & 31;
    const int half = l >> 4;
    const int gate = (l >> 2) & 3;
    const int cq   = l & 3;
    const int cell_loc = w * 4 + cq;    // 0..31 in this CTA's chunk
    const int grow = gate * CELL + (int)rank * 32 + cell_loc;

    // Half-row of W_hh register-resident as packed f32x2
    uint64_t wq[32];
    {
        const ulonglong2* wp = reinterpret_cast<const ulonglong2*>(Whh + grow * CELL + half * 64);
        #pragma unroll
        for (int i = 0; i < 16; i++) {
            ulonglong2 v = wp[i];
            wq[2*i] = v.x; wq[2*i+1] = v.y;
        }
    }

    if (t < CELL) h_hist[t] = 0.0f;     // h0 = 0
    const uint32_t hbase_la = smem_u32(h_hist);
    const uint32_t mbar_la  = smem_u32(&mbar);
    if (t == 0) {
        mbar_init(mbar_la, 1);
        mbar_arrive_expect_tx(mbar_la, H_BYTES_PER_STEP);   // arm phase 0 up front
    }
    __syncthreads();
    cluster_sync();                     // all 4 CTAs' armed mbarriers visible

    uint32_t peer_h[NREC], peer_m[NREC];
    #pragma unroll
    for (uint32_t r = 0; r < NREC; r++) {
        peer_h[r] = mapa_rank(hbase_la, r);
        peer_m[r] = mapa_rank(mbar_la, r);
    }

    if (t == 0) { while (ld_acq_u32(&g_ctr[0]) < NPRE) { } }
    __syncthreads();

    float c = 0.0f;                      // lanes l<4 own cell rank*32 + cell_loc
    float xwv = g_xw[grow];

    // activation: sig(x) = 0.5*tanh(0.5x)+0.5 ; gate 2 uses tanh directly
    const float asc_in  = (gate == 2) ? 1.0f : 0.5f;
    const float asc_out = (gate == 2) ? 1.0f : 0.5f;
    const float aoff    = (gate == 2) ? 0.0f : 0.5f;

    for (int step = 0; step < STEPS; step++) {
        // half-row dot: 16x LDS.v2.b64 + 32x fma.rn.f32x2
        uint32_t hb = hbase_la + (uint32_t)(step * CELL * 4 + half * 256);
        uint64_t acc0 = 0ull, acc1 = 0ull;
        #pragma unroll
        for (int i = 0; i < 16; i++) {
            uint64_t h01, h23;
            asm volatile("ld.shared.v2.b64 {%0,%1}, [%2];"
                         : "=l"(h01), "=l"(h23) : "r"(hb + 16u * i));
            asm volatile("fma.rn.f32x2 %0, %1, %2, %0;" : "+l"(acc0) : "l"(wq[2*i]),   "l"(h01));
            asm volatile("fma.rn.f32x2 %0, %1, %2, %0;" : "+l"(acc1) : "l"(wq[2*i+1]), "l"(h23));
        }
        uint64_t accs;
        asm("add.rn.f32x2 %0, %1, %2;" : "=l"(accs) : "l"(acc0), "l"(acc1));
        uint32_t plo, phi;
        asm("mov.b64 {%0,%1}, %2;" : "=r"(plo), "=r"(phi) : "l"(accs));
        float partial = __uint_as_float(plo) + __uint_as_float(phi);

        float full = partial + __shfl_xor_sync(0xffffffffu, partial, 16);
        float gv   = full + xwv;
        float a    = fmaf(asc_out, ftanh_mufu(asc_in * gv), aoff);   // MUFU.TANH

        // gather the 4 gates of cell (l&3)
        int srcq = l & 3;
        float iv = __shfl_sync(0xffffffffu, a, srcq);
        float fv = __shfl_sync(0xffffffffu, a, 4 + srcq);
        float g2 = __shfl_sync(0xffffffffu, a, 8 + srcq);
        float ov = __shfl_sync(0xffffffffu, a, 12 + srcq);

        // all lanes compute (garbage for l>=4, never read)
        c = fv * c + iv * g2;
        float h = ov * ftanh_mufu(c);

        // warp's 4 h values -> lane 0, one st.async.v4 per rank
        float h0 = __shfl_sync(0xffffffffu, h, 0);
        float h1 = __shfl_sync(0xffffffffu, h, 1);
        float h2 = __shfl_sync(0xffffffffu, h, 2);
        float h3 = __shfl_sync(0xffffffffu, h, 3);
        if (l == 0) {
            uint32_t off = (uint32_t)(((step + 1) * CELL + (int)rank * 32 + w * 4) * 4);
            #pragma unroll
            for (uint32_t r = 0; r < NREC; r++)
                st_async_v4(peer_h[r] + off, h0, h1, h2, h3, peer_m[r]);
        }

        if (step + 1 < STEPS) xwv = g_xw[(step + 1) * 512 + grow];  // hide L2 latency
        mbar_wait_parity(mbar_la, (uint32_t)(step & 1));
        // re-arm for next phase, off the critical path (early tx before arm is
        // spec-legal negative-tx accounting)
        if (t == 0 && step + 1 < STEPS)
            mbar_arrive_expect_tx(mbar_la, H_BYTES_PER_STEP);
    }

    // ---------------- Phase C: softmax heads, 5 steps per CTA ----------------
    if (t < 5 * NOUT) {
        int sl = t / NOUT;
        int o  = t % NOUT;
        int s  = (int)rank * 5 + sl;
        const float4* hv = reinterpret_cast<const float4*>(h_hist + (s + 1) * CELL);
        const float4* fv = reinterpret_cast<const float4*>(fcW + ((s & 3) * NOUT + o) * CELL);
        float a0 = 0.f, a1 = 0.f, a2 = 0.f, a3 = 0.f;
        #pragma unroll
        for (int i = 0; i < 32; i++) {
            float4 h4 = hv[i];
            float4 w4 = fv[i];
            a0 += h4.x * w4.x; a1 += h4.y * w4.y;
            a2 += h4.z * w4.z; a3 += h4.w * w4.w;
        }
        sm_log[sl][o] = (a0 + a1) + (a2 + a3) + fcb[(s & 3) * NOUT + o];
    }
    __syncthreads();
    if (t < 5) {
        int s = (int)rank * 5 + t;
        float m = sm_log[t][0];
        #pragma unroll
        for (int o = 1; o < NOUT; o++) m = fmaxf(m, sm_log[t][o]);
        float e[NOUT];
        float sum = 0.f;
        #pragma unroll
        for (int o = 0; o < NOUT; o++) { e[o] = expf(sm_log[t][o] - m); sum += e[o]; }
        float inv = 1.0f / sum;
        #pragma unroll
        for (int o = 0; o < NOUT; o++) out[s * NOUT + o] = e[o] * inv;
    }

    // self-reset the phase-A counter for the next graph replay.
    // Safe: every recurrence CTA passed the ctr==NPRE wait before step 0's
    // exchange could complete, and we are past all 20 exchanges here.
    if (b == 0 && t == 0) g_ctr[0] = 0u;
}

extern "C" void kernel_launch(void* const* d_in, const int* in_sizes, int n_in,
                              void* d_out, int out_size) {
    const int*   net       = (const int*)  d_in[0];
    // d_in[1] = reward (unused)
    const float* emb_start = (const float*)d_in[2];
    const float* emb_keys  = (const float*)d_in[3];
    const float* fcW       = (const float*)d_in[4];
    const float* fcb       = (const float*)d_in[5];
    const float* Wih       = (const float*)d_in[6];
    const float* Whh       = (const float*)d_in[7];
    const float* bih       = (const float*)d_in[8];
    const float* bhh       = (const float*)d_in[9];
    float* out = (float*)d_out;

    nas_policy_kernel<<<NPRE, NTH>>>(net, emb_start, emb_keys, fcW, fcb,
                                     Wih, Whh, bih, bhh, out);
}